// round 14
// baseline (speedup 1.0000x reference)
#include <cuda_runtime.h>
#include <cuda_fp16.h>
#include <math.h>
#include <stdint.h>

#define BB 4
#define NN 4096
#define CC 256
#define L2E 1.4426950408889634f

typedef unsigned long long ull;
typedef unsigned int u32;

// ---------------- scratch (device globals; no allocation allowed) ----------
__device__ __half d_f16p[BB * NN * 64];                 // [n][0:32)=f_hi, [32:64)=f_lo
__device__ __half d_g16[BB * NN * 64];                  // [n][0:32)=g_hi, [32:64)=g_lo
__device__ __half d_h16T[(size_t)BB * CC * NN];         // [b][c][n]
__device__ float  d_o[(size_t)BB * NN * CC];            // attention out fp32

// ---------------- mma / cp.async / ldmatrix helpers --------------------------
__device__ __forceinline__ void mma16816(float* c, const u32* a, u32 b0, u32 b1) {
    asm volatile(
        "mma.sync.aligned.m16n8k16.row.col.f32.f16.f16.f32 "
        "{%0,%1,%2,%3}, {%4,%5,%6,%7}, {%8,%9}, {%0,%1,%2,%3};"
        : "+f"(c[0]), "+f"(c[1]), "+f"(c[2]), "+f"(c[3])
        : "r"(a[0]), "r"(a[1]), "r"(a[2]), "r"(a[3]), "r"(b0), "r"(b1));
}
__device__ __forceinline__ void ldsm4(u32& r0, u32& r1, u32& r2, u32& r3, u32 addr) {
    asm volatile("ldmatrix.sync.aligned.m8n8.x4.shared.b16 {%0,%1,%2,%3}, [%4];"
                 : "=r"(r0), "=r"(r1), "=r"(r2), "=r"(r3) : "r"(addr));
}
__device__ __forceinline__ u32 smem_u32(const void* p) {
    u32 a;
    asm("{ .reg .u64 t; cvta.to.shared.u64 t, %1; cvt.u32.u64 %0, t; }" : "=r"(a) : "l"(p));
    return a;
}
__device__ __forceinline__ void cpa16(u32 s, const void* g) {
    asm volatile("cp.async.cg.shared.global [%0], [%1], 16;" :: "r"(s), "l"(g));
}
#define CP_COMMIT() asm volatile("cp.async.commit_group;" ::: "memory")
#define CP_WAIT0()  asm volatile("cp.async.wait_group 0;" ::: "memory")
#define CP_WAIT1()  asm volatile("cp.async.wait_group 1;" ::: "memory")

__device__ __forceinline__ u32 f2h2u(float a, float b) {
    __half2 h = __floats2half2_rn(a, b);
    return *(u32*)&h;
}

// ===========================================================================
// Fused f/g/h projection, HMMA 3-term.  CTA = 64 rows, 320 threads.
// (byte-identical to measured R11/R13: ~60 us)
// ===========================================================================
#define SA_STRIDE 40
#define SW_STRIDE 36
#define FGH_NCOL 320
#define FGH_SMEM (20480 + 2 * (FGH_NCOL * SW_STRIDE * 2))

__global__ __launch_bounds__(320) void k_fgh(
    const float* __restrict__ x,
    const float* __restrict__ Wh, const float* __restrict__ bh,
    const float* __restrict__ Wf, const float* __restrict__ bf,
    const float* __restrict__ Wg, const float* __restrict__ bg)
{
    extern __shared__ __align__(16) char sm[];
    float* sA[2] = { (float*)sm, (float*)(sm + 10240) };
    __half* sWhi = (__half*)(sm + 20480);
    __half* sWlo = (__half*)(sm + 20480 + FGH_NCOL * SW_STRIDE * 2);
    u32 sAu[2] = { smem_u32(sA[0]), smem_u32(sA[1]) };

    const int tid = threadIdx.x, w = tid >> 5, lane = tid & 31;
    const int qr = lane >> 2, kq2 = (lane & 3) << 1;
    const int row0 = blockIdx.x * 64;
    const char* xrow = (const char*)(x + (size_t)row0 * 256);

    float acc[4][4][4] = {};

    if (tid < 256) {
#pragma unroll
        for (int i = 0; i < 2; i++) {
            int e = tid * 2 + i; int r = e >> 3, s = e & 7;
            cpa16(sAu[0] + r * 160 + s * 16, xrow + (size_t)r * 1024 + s * 16);
        }
    }
    CP_COMMIT();

    for (int s = 0; s < 8; s++) {
        const int k0 = s * 32;
        __syncthreads();
        if (s < 7) {
            if (tid < 256) {
#pragma unroll
                for (int i = 0; i < 2; i++) {
                    int e = tid * 2 + i; int r = e >> 3, seg = e & 7;
                    cpa16(sAu[(s + 1) & 1] + r * 160 + seg * 16,
                          xrow + (size_t)r * 1024 + (k0 + 32) * 4 + seg * 16);
                }
            }
        }
        CP_COMMIT();
        {
            const float* wp; int stride;
            if (tid < 256)      { wp = Wh + tid;         stride = 256; }
            else if (tid < 288) { wp = Wf + (tid - 256); stride = 32; }
            else                { wp = Wg + (tid - 288); stride = 32; }
#pragma unroll
            for (int k = 0; k < 32; k++) {
                float v = wp[(size_t)(k0 + k) * stride];
                __half hi = __float2half_rn(v);
                sWhi[tid * SW_STRIDE + k] = hi;
                sWlo[tid * SW_STRIDE + k] = __float2half_rn(v - __half2float(hi));
            }
        }
        if (s < 7) { CP_WAIT1(); } else { CP_WAIT0(); }
        __syncthreads();

        const float* sa = sA[s & 1];
#pragma unroll
        for (int kc = 0; kc < 2; kc++) {
            u32 AH[4][4], AL[4][4];
#pragma unroll
            for (int rg = 0; rg < 4; rg++) {
                const float* base = sa + (rg * 16 + qr) * SA_STRIDE + kc * 16 + kq2;
                float2 v0 = *(const float2*)(base);
                float2 v1 = *(const float2*)(base + 8 * SA_STRIDE);
                float2 v2 = *(const float2*)(base + 8);
                float2 v3 = *(const float2*)(base + 8 * SA_STRIDE + 8);
                __half2 h;
                h = __floats2half2_rn(v0.x, v0.y); AH[rg][0] = *(u32*)&h;
                float2 r0 = __half22float2(h);
                h = __floats2half2_rn(v0.x - r0.x, v0.y - r0.y); AL[rg][0] = *(u32*)&h;
                h = __floats2half2_rn(v1.x, v1.y); AH[rg][1] = *(u32*)&h;
                float2 r1 = __half22float2(h);
                h = __floats2half2_rn(v1.x - r1.x, v1.y - r1.y); AL[rg][1] = *(u32*)&h;
                h = __floats2half2_rn(v2.x, v2.y); AH[rg][2] = *(u32*)&h;
                float2 r2 = __half22float2(h);
                h = __floats2half2_rn(v2.x - r2.x, v2.y - r2.y); AL[rg][2] = *(u32*)&h;
                h = __floats2half2_rn(v3.x, v3.y); AH[rg][3] = *(u32*)&h;
                float2 r3 = __half22float2(h);
                h = __floats2half2_rn(v3.x - r3.x, v3.y - r3.y); AL[rg][3] = *(u32*)&h;
            }
#pragma unroll
            for (int nt = 0; nt < 4; nt++) {
                const __half* bp  = sWhi + (w * 32 + nt * 8 + qr) * SW_STRIDE + kc * 16 + kq2;
                const __half* bpl = sWlo + (w * 32 + nt * 8 + qr) * SW_STRIDE + kc * 16 + kq2;
                u32 bh0 = *(const u32*)bp,  bh1 = *(const u32*)(bp + 8);
                u32 bl0 = *(const u32*)bpl, bl1 = *(const u32*)(bpl + 8);
#pragma unroll
                for (int rg = 0; rg < 4; rg++) {
                    mma16816(acc[rg][nt], AH[rg], bh0, bh1);
                    mma16816(acc[rg][nt], AL[rg], bh0, bh1);
                    mma16816(acc[rg][nt], AH[rg], bl0, bl1);
                }
            }
        }
    }
    __syncthreads();

    if (w < 8) {
        __half* reg = (__half*)(sm + w * 4096);
#pragma unroll
        for (int nt = 0; nt < 4; nt++) {
            int cl = nt * 8 + kq2;
            float b0 = bh[w * 32 + cl], b1 = bh[w * 32 + cl + 1];
#pragma unroll
            for (int rg = 0; rg < 4; rg++) {
                int r = rg * 16 + qr;
                __half2 p0 = __floats2half2_rn(acc[rg][nt][0] + b0, acc[rg][nt][1] + b1);
                __half2 p1 = __floats2half2_rn(acc[rg][nt][2] + b0, acc[rg][nt][3] + b1);
                reg[cl * 64 + r]           = __low2half(p0);
                reg[(cl + 1) * 64 + r]     = __high2half(p0);
                reg[cl * 64 + r + 8]       = __low2half(p1);
                reg[(cl + 1) * 64 + r + 8] = __high2half(p1);
            }
        }
        __syncwarp();
        const size_t b = (size_t)(row0 >> 12);
        const int nl = row0 & 4095;
        __half* dstb = d_h16T + b * (size_t)CC * NN;
#pragma unroll
        for (int i = 0; i < 8; i++) {
            int u = i * 32 + lane;
            int cl = u >> 3, seg = u & 7;
            *(uint4*)(dstb + (size_t)(w * 32 + cl) * NN + nl + seg * 8) =
                *(const uint4*)(reg + cl * 64 + seg * 8);
        }
    } else {
        __half* reg = (__half*)(sm + 32768 + (w - 8) * 8192);
        const float* bias = (w == 8) ? bf : bg;
#pragma unroll
        for (int nt = 0; nt < 4; nt++) {
            int cl = nt * 8 + kq2;
            float b0 = bias[cl], b1 = bias[cl + 1];
#pragma unroll
            for (int rg = 0; rg < 4; rg++) {
#pragma unroll
                for (int half = 0; half < 2; half++) {
                    int r = rg * 16 + qr + half * 8;
                    float v0 = acc[rg][nt][half * 2] + b0;
                    float v1 = acc[rg][nt][half * 2 + 1] + b1;
                    __half h0 = __float2half_rn(v0);
                    __half h1 = __float2half_rn(v1);
                    reg[r * 64 + cl] = h0;
                    reg[r * 64 + cl + 1] = h1;
                    reg[r * 64 + 32 + cl] = __float2half_rn(v0 - __half2float(h0));
                    reg[r * 64 + 32 + cl + 1] = __float2half_rn(v1 - __half2float(h1));
                }
            }
        }
        __syncwarp();
        __half* dst = ((w == 8) ? d_f16p : d_g16) + (size_t)row0 * 64;
#pragma unroll
        for (int i = 0; i < 16; i++) {
            int u = i * 32 + lane;
            int r = u >> 3, seg = u & 7;
            *(uint4*)(dst + (size_t)r * 64 + seg * 8) = *(const uint4*)(reg + r * 64 + seg * 8);
        }
    }
}

// ===========================================================================
// v projection + residual, HMMA 3-term (byte-identical to measured R11/R13).
// ===========================================================================
#define VP_SMEM (20480 + 2 * (256 * SW_STRIDE * 2))

__global__ __launch_bounds__(256) void k_vproj(
    const float* __restrict__ Wv, const float* __restrict__ bv,
    const float* __restrict__ x, float* __restrict__ out)
{
    extern __shared__ __align__(16) char sm[];
    float* sA[2] = { (float*)sm, (float*)(sm + 10240) };
    __half* sWhi = (__half*)(sm + 20480);
    __half* sWlo = (__half*)(sm + 20480 + 256 * SW_STRIDE * 2);
    u32 sAu[2] = { smem_u32(sA[0]), smem_u32(sA[1]) };

    const int tid = threadIdx.x, w = tid >> 5, lane = tid & 31;
    const int qr = lane >> 2, kq2 = (lane & 3) << 1;
    const int row0 = blockIdx.x * 64;
    const char* arow = (const char*)(d_o + (size_t)row0 * 256);

    float acc[4][4][4] = {};

#pragma unroll
    for (int i = 0; i < 2; i++) {
        int e = tid * 2 + i; int r = e >> 3, s = e & 7;
        cpa16(sAu[0] + r * 160 + s * 16, arow + (size_t)r * 1024 + s * 16);
    }
    CP_COMMIT();

    for (int s = 0; s < 8; s++) {
        const int k0 = s * 32;
        __syncthreads();
        if (s < 7) {
#pragma unroll
            for (int i = 0; i < 2; i++) {
                int e = tid * 2 + i; int r = e >> 3, seg = e & 7;
                cpa16(sAu[(s + 1) & 1] + r * 160 + seg * 16,
                      arow + (size_t)r * 1024 + (k0 + 32) * 4 + seg * 16);
            }
        }
        CP_COMMIT();
        {
#pragma unroll
            for (int k = 0; k < 32; k++) {
                float v = Wv[(size_t)(k0 + k) * 256 + tid];
                __half hi = __float2half_rn(v);
                sWhi[tid * SW_STRIDE + k] = hi;
                sWlo[tid * SW_STRIDE + k] = __float2half_rn(v - __half2float(hi));
            }
        }
        if (s < 7) { CP_WAIT1(); } else { CP_WAIT0(); }
        __syncthreads();

        const float* sa = sA[s & 1];
#pragma unroll
        for (int kc = 0; kc < 2; kc++) {
            u32 AH[4][4], AL[4][4];
#pragma unroll
            for (int rg = 0; rg < 4; rg++) {
                const float* base = sa + (rg * 16 + qr) * SA_STRIDE + kc * 16 + kq2;
                float2 v0 = *(const float2*)(base);
                float2 v1 = *(const float2*)(base + 8 * SA_STRIDE);
                float2 v2 = *(const float2*)(base + 8);
                float2 v3 = *(const float2*)(base + 8 * SA_STRIDE + 8);
                __half2 h;
                h = __floats2half2_rn(v0.x, v0.y); AH[rg][0] = *(u32*)&h;
                float2 r0 = __half22float2(h);
                h = __floats2half2_rn(v0.x - r0.x, v0.y - r0.y); AL[rg][0] = *(u32*)&h;
                h = __floats2half2_rn(v1.x, v1.y); AH[rg][1] = *(u32*)&h;
                float2 r1 = __half22float2(h);
                h = __floats2half2_rn(v1.x - r1.x, v1.y - r1.y); AL[rg][1] = *(u32*)&h;
                h = __floats2half2_rn(v2.x, v2.y); AH[rg][2] = *(u32*)&h;
                float2 r2 = __half22float2(h);
                h = __floats2half2_rn(v2.x - r2.x, v2.y - r2.y); AL[rg][2] = *(u32*)&h;
                h = __floats2half2_rn(v3.x, v3.y); AH[rg][3] = *(u32*)&h;
                float2 r3 = __half22float2(h);
                h = __floats2half2_rn(v3.x - r3.x, v3.y - r3.y); AL[rg][3] = *(u32*)&h;
            }
#pragma unroll
            for (int nt = 0; nt < 4; nt++) {
                const __half* bp  = sWhi + (w * 32 + nt * 8 + qr) * SW_STRIDE + kc * 16 + kq2;
                const __half* bpl = sWlo + (w * 32 + nt * 8 + qr) * SW_STRIDE + kc * 16 + kq2;
                u32 bh0 = *(const u32*)bp,  bh1 = *(const u32*)(bp + 8);
                u32 bl0 = *(const u32*)bpl, bl1 = *(const u32*)(bpl + 8);
#pragma unroll
                for (int rg = 0; rg < 4; rg++) {
                    mma16816(acc[rg][nt], AH[rg], bh0, bh1);
                    mma16816(acc[rg][nt], AL[rg], bh0, bh1);
                    mma16816(acc[rg][nt], AH[rg], bl0, bl1);
                }
            }
        }
    }

#pragma unroll
    for (int nt = 0; nt < 4; nt++) {
        int c = w * 32 + nt * 8 + kq2;
        float b0 = bv[c], b1 = bv[c + 1];
#pragma unroll
        for (int rg = 0; rg < 4; rg++) {
#pragma unroll
            for (int half = 0; half < 2; half++) {
                int r = row0 + rg * 16 + qr + half * 8;
                float2 xr = *(const float2*)&x[(size_t)r * 256 + c];
                float2 o;
                o.x = acc[rg][nt][half * 2] + b0 + xr.x;
                o.y = acc[rg][nt][half * 2 + 1] + b1 + xr.y;
                *(float2*)&out[(size_t)r * 256 + c] = o;
            }
        }
    }
}

// ===========================================================================
// HMMA flash attention — SINGLE PASS (exact): per tile, sweep 1 computes S
// (fp32) into warp-private smem + tile max; rescale oa by exp(m_old-m_new);
// sweep 2 exps against tile-inclusive max (fp16-safe) and accumulates O.
// CTA = 64 q rows (4 warps, 128 thr), key-tile 64, grid 256.
// ===========================================================================
#define SF_STRIDE 144
#define SH_STRIDE 144
#define SF_BYTES (64 * SF_STRIDE)      // 9216
#define SH_BYTES (256 * SH_STRIDE)     // 36864
#define SS_STRIDE 68                   // floats per S row
#define SS_OFF (2 * SF_BYTES + 2 * SH_BYTES)          // 92160
#define ATTN_SMEM (SS_OFF + 64 * SS_STRIDE * 4)       // 109568
#define ONES_H2 0x3C003C00u

__global__ __launch_bounds__(128) void k_attn()
{
    extern __shared__ __align__(16) char dsm[];
    u32 sFu[2] = { smem_u32(dsm), smem_u32(dsm + SF_BYTES) };
    u32 sHu[2] = { smem_u32(dsm + 2 * SF_BYTES), smem_u32(dsm + 2 * SF_BYTES + SH_BYTES) };
    float* sS = (float*)(dsm + SS_OFF);

    const int tid = threadIdx.x;
    const int w = tid >> 5, lane = tid & 31;
    const int qr = lane >> 2;
    const int kq = (lane & 3) << 1;
    const int b = blockIdx.y, q0 = blockIdx.x * 64;

    const int mat = lane >> 3, ln8 = lane & 7;
    const u32 fOffLane = (u32)((8 * (mat >> 1) + ln8) * SF_STRIDE + (mat & 1) * 16);
    const u32 hOffLane = (u32)((8 * (mat >> 1) + ln8) * SH_STRIDE + (mat & 1) * 16);

    const char* fglob = (const char*)(d_f16p + (size_t)b * NN * 64);
    const char* hglob = (const char*)(d_h16T + (size_t)b * CC * NN);

    u32 Ghi[2][4], Glo[2][4];
    {
        const char* g0 = (const char*)(d_g16 + (size_t)(b * NN + q0 + 16 * w) * 64);
#pragma unroll
        for (int c = 0; c < 2; ++c) {
            int kb = 16 * c + kq;
            Ghi[c][0] = *(const u32*)(g0 + (size_t)qr * 128 + kb * 2);
            Ghi[c][1] = *(const u32*)(g0 + (size_t)(qr + 8) * 128 + kb * 2);
            Ghi[c][2] = *(const u32*)(g0 + (size_t)qr * 128 + (kb + 8) * 2);
            Ghi[c][3] = *(const u32*)(g0 + (size_t)(qr + 8) * 128 + (kb + 8) * 2);
            Glo[c][0] = *(const u32*)(g0 + (size_t)qr * 128 + 64 + kb * 2);
            Glo[c][1] = *(const u32*)(g0 + (size_t)(qr + 8) * 128 + 64 + kb * 2);
            Glo[c][2] = *(const u32*)(g0 + (size_t)qr * 128 + 64 + (kb + 8) * 2);
            Glo[c][3] = *(const u32*)(g0 + (size_t)(qr + 8) * 128 + 64 + (kb + 8) * 2);
        }
    }

    float oa[32][4];
#pragma unroll
    for (int j = 0; j < 32; ++j) { oa[j][0] = oa[j][1] = oa[j][2] = oa[j][3] = 0.f; }
    float lacc[4] = {0.f, 0.f, 0.f, 0.f};
    float mL0 = -1e30f, mL1 = -1e30f;

    // preload tile 0 (F + H)
    {
#pragma unroll
        for (int i = 0; i < 4; i++) {
            int e = tid + 128 * i; int row = e >> 3, q = e & 7;
            cpa16(sFu[0] + row * SF_STRIDE + q * 16, fglob + row * 128 + q * 16);
        }
#pragma unroll
        for (int i = 0; i < 16; i++) {
            int e = tid + 128 * i; int row = e >> 3, q = e & 7;
            cpa16(sHu[0] + row * SH_STRIDE + q * 16, hglob + (size_t)row * 8192 + q * 16);
        }
        CP_COMMIT();
    }

    float* sSw = sS + (16 * w + qr) * SS_STRIDE + kq;   // this thread's S base

#pragma unroll 1
    for (int kt = 0; kt < 64; ++kt) {
        if (kt < 63) {
            u32 sfb = sFu[(kt + 1) & 1], shb = sHu[(kt + 1) & 1];
            const char* gf = fglob + (size_t)(kt + 1) * 8192;
            const char* gh = hglob + (size_t)(kt + 1) * 128;
#pragma unroll
            for (int i = 0; i < 4; i++) {
                int e = tid + 128 * i; int row = e >> 3, q = e & 7;
                cpa16(sfb + row * SF_STRIDE + q * 16, gf + row * 128 + q * 16);
            }
#pragma unroll
            for (int i = 0; i < 16; i++) {
                int e = tid + 128 * i; int row = e >> 3, q = e & 7;
                cpa16(shb + row * SH_STRIDE + q * 16, gh + (size_t)row * 8192 + q * 16);
            }
            CP_COMMIT();
            CP_WAIT1();
        } else {
            CP_WAIT0();
        }
        __syncthreads();

        const u32 fbu = sFu[kt & 1];
        const u32 hbu = sHu[kt & 1];

        // ---- sweep 1: S -> smem (fp32) + tile max ----
        float tmax0 = -1e30f, tmax1 = -1e30f;
#pragma unroll
        for (int kk = 0; kk < 4; ++kk) {
            float cA[4] = {0.f, 0.f, 0.f, 0.f};
            float cB[4] = {0.f, 0.f, 0.f, 0.f};
            const u32 fRow = fbu + (u32)(16 * kk * SF_STRIDE) + fOffLane;
#pragma unroll
            for (int c = 0; c < 2; ++c) {
                u32 ah0, ah1, bh0, bh1, al0, al1, bl0, bl1;
                ldsm4(ah0, ah1, bh0, bh1, fRow + 32 * c);
                ldsm4(al0, al1, bl0, bl1, fRow + 32 * c + 64);
                mma16816(cA, Ghi[c], ah0, ah1);
                mma16816(cB, Ghi[c], bh0, bh1);
                mma16816(cA, Glo[c], ah0, ah1);
                mma16816(cB, Glo[c], bh0, bh1);
                mma16816(cA, Ghi[c], al0, al1);
                mma16816(cB, Ghi[c], bl0, bl1);
            }
            tmax0 = fmaxf(tmax0, fmaxf(fmaxf(cA[0], cA[1]), fmaxf(cB[0], cB[1])));
            tmax1 = fmaxf(tmax1, fmaxf(fmaxf(cA[2], cA[3]), fmaxf(cB[2], cB[3])));
            float* sp = sSw + 16 * kk;
            *(float2*)(sp)                      = make_float2(cA[0], cA[1]);
            *(float2*)(sp + 8)                  = make_float2(cB[0], cB[1]);
            *(float2*)(sp + 8 * SS_STRIDE)      = make_float2(cA[2], cA[3]);
            *(float2*)(sp + 8 * SS_STRIDE + 8)  = make_float2(cB[2], cB[3]);
        }

        // ---- rescale (exact online softmax) ----
        tmax0 = fmaxf(tmax0, __shfl_xor_sync(0xffffffffu, tmax0, 1));
        tmax0 = fmaxf(tmax0, __shfl_xor_sync(0xffffffffu, tmax0, 2));
        tmax1 = fmaxf(tmax1, __shfl_xor_sync(0xffffffffu, tmax1, 1));
        tmax1 = fmaxf(tmax1, __shfl_xor_sync(0xffffffffu, tmax1, 2));
        float t0L = tmax0 * L2E, t1L = tmax1 * L2E;
        if (t0L > mL0) {
            float a = exp2f(mL0 - t0L);
#pragma unroll
            for (int j = 0; j < 32; ++j) { oa[j][0] *= a; oa[j][1] *= a; }
            lacc[0] *= a; lacc[1] *= a;
            mL0 = t0L;
        }
        if (t1L > mL1) {
            float a = exp2f(mL1 - t1L);
#pragma unroll
            for (int j = 0; j < 32; ++j) { oa[j][2] *= a; oa[j][3] *= a; }
            lacc[2] *= a; lacc[3] *= a;
            mL1 = t1L;
        }

        // ---- sweep 2: P (fp16, tile-inclusive max => no overflow) + O ----
#pragma unroll
        for (int kk = 0; kk < 4; ++kk) {
            const float* sp = sSw + 16 * kk;
            float2 a01 = *(const float2*)(sp);
            float2 b01 = *(const float2*)(sp + 8);
            float2 a23 = *(const float2*)(sp + 8 * SS_STRIDE);
            float2 b23 = *(const float2*)(sp + 8 * SS_STRIDE + 8);
            u32 P[4];
            P[0] = f2h2u(exp2f(fmaf(a01.x, L2E, -mL0)), exp2f(fmaf(a01.y, L2E, -mL0)));
            P[1] = f2h2u(exp2f(fmaf(a23.x, L2E, -mL1)), exp2f(fmaf(a23.y, L2E, -mL1)));
            P[2] = f2h2u(exp2f(fmaf(b01.x, L2E, -mL0)), exp2f(fmaf(b01.y, L2E, -mL0)));
            P[3] = f2h2u(exp2f(fmaf(b23.x, L2E, -mL1)), exp2f(fmaf(b23.y, L2E, -mL1)));

            mma16816(lacc, P, ONES_H2, ONES_H2);

            const u32 hRow = hbu + (u32)(32 * kk) + hOffLane;
#pragma unroll
            for (int pr = 0; pr < 16; ++pr) {
                u32 r0, r1, r2, r3;
                ldsm4(r0, r1, r2, r3, hRow + (u32)(16 * pr * SH_STRIDE));
                mma16816(oa[2 * pr], P, r0, r1);
                mma16816(oa[2 * pr + 1], P, r2, r3);
            }
        }
        __syncthreads();
    }

    // ---- epilogue: o = O / li ----
    {
        float inv0 = 1.0f / lacc[0];
        float inv1 = 1.0f / lacc[2];
        float* op = d_o + ((size_t)b * NN + q0 + 16 * w) * 256;
#pragma unroll
        for (int j2 = 0; j2 < 32; ++j2) {
            int cc = 8 * j2 + kq;
            *(float2*)(op + (size_t)qr * 256 + cc) =
                make_float2(oa[j2][0] * inv0, oa[j2][1] * inv0);
            *(float2*)(op + (size_t)(qr + 8) * 256 + cc) =
                make_float2(oa[j2][2] * inv1, oa[j2][3] * inv1);
        }
    }
}

// ---------------------------------------------------------------------------
extern "C" void kernel_launch(void* const* d_in, const int* in_sizes, int n_in,
                              void* d_out, int out_size)
{
    const float* x  = (const float*)d_in[0];
    const float* Wf = (const float*)d_in[1];
    const float* bf = (const float*)d_in[2];
    const float* Wg = (const float*)d_in[3];
    const float* bg = (const float*)d_in[4];
    const float* Wh = (const float*)d_in[5];
    const float* bh = (const float*)d_in[6];
    const float* Wv = (const float*)d_in[7];
    const float* bv = (const float*)d_in[8];
    float* out = (float*)d_out;

    cudaFuncSetAttribute(k_fgh,   cudaFuncAttributeMaxDynamicSharedMemorySize, FGH_SMEM);
    cudaFuncSetAttribute(k_vproj, cudaFuncAttributeMaxDynamicSharedMemorySize, VP_SMEM);
    cudaFuncSetAttribute(k_attn,  cudaFuncAttributeMaxDynamicSharedMemorySize, ATTN_SMEM);

    k_fgh<<<256, 320, FGH_SMEM>>>(x, Wh, bh, Wf, bf, Wg, bg);
    k_attn<<<dim3(64, 4), 128, ATTN_SMEM>>>();
    k_vproj<<<256, 256, VP_SMEM>>>(Wv, bv, x, out);
}

// round 17
// speedup vs baseline: 1.1227x; 1.1227x over previous
#include <cuda_runtime.h>
#include <cuda_fp16.h>
#include <math.h>
#include <stdint.h>

#define BB 4
#define NN 4096
#define CC 256
#define L2E 1.4426950408889634f

typedef unsigned long long ull;
typedef unsigned int u32;

// ---------------- scratch (device globals; no allocation allowed) ----------
__device__ __half d_f16p[BB * NN * 64];                 // [n][0:32)=f_hi, [32:64)=f_lo
__device__ __half d_g16[BB * NN * 64];                  // [n][0:32)=g_hi, [32:64)=g_lo
__device__ __half d_h16T[(size_t)BB * CC * NN];         // [b][c][n]
__device__ float  d_o[(size_t)BB * NN * CC];            // attention out fp32

// ---------------- mma / cp.async / ldmatrix helpers --------------------------
__device__ __forceinline__ void mma16816(float* c, const u32* a, u32 b0, u32 b1) {
    asm volatile(
        "mma.sync.aligned.m16n8k16.row.col.f32.f16.f16.f32 "
        "{%0,%1,%2,%3}, {%4,%5,%6,%7}, {%8,%9}, {%0,%1,%2,%3};"
        : "+f"(c[0]), "+f"(c[1]), "+f"(c[2]), "+f"(c[3])
        : "r"(a[0]), "r"(a[1]), "r"(a[2]), "r"(a[3]), "r"(b0), "r"(b1));
}
__device__ __forceinline__ void ldsm4(u32& r0, u32& r1, u32& r2, u32& r3, u32 addr) {
    asm volatile("ldmatrix.sync.aligned.m8n8.x4.shared.b16 {%0,%1,%2,%3}, [%4];"
                 : "=r"(r0), "=r"(r1), "=r"(r2), "=r"(r3) : "r"(addr));
}
__device__ __forceinline__ u32 smem_u32(const void* p) {
    u32 a;
    asm("{ .reg .u64 t; cvta.to.shared.u64 t, %1; cvt.u32.u64 %0, t; }" : "=r"(a) : "l"(p));
    return a;
}
__device__ __forceinline__ void cpa16(u32 s, const void* g) {
    asm volatile("cp.async.cg.shared.global [%0], [%1], 16;" :: "r"(s), "l"(g));
}
#define CP_COMMIT() asm volatile("cp.async.commit_group;" ::: "memory")
#define CP_WAIT0()  asm volatile("cp.async.wait_group 0;" ::: "memory")
#define CP_WAIT1()  asm volatile("cp.async.wait_group 1;" ::: "memory")

__device__ __forceinline__ u32 f2h2u(float a, float b) {
    __half2 h = __floats2half2_rn(a, b);
    return *(u32*)&h;
}

// ---------------- shared A-fragment conversion (fp32 smem -> hi/lo f16) ------
#define SA_STRIDE 40
#define SW_STRIDE 36

#define CVT_A_FRAGS4(sa)                                                       \
    u32 AH[4][4], AL[4][4];                                                    \
    _Pragma("unroll")                                                          \
    for (int rg = 0; rg < 4; rg++) {                                           \
        const float* base = (sa) + (rg * 16 + qr) * SA_STRIDE + kc * 16 + kq2; \
        float2 v0 = *(const float2*)(base);                                    \
        float2 v1 = *(const float2*)(base + 8 * SA_STRIDE);                    \
        float2 v2 = *(const float2*)(base + 8);                                \
        float2 v3 = *(const float2*)(base + 8 * SA_STRIDE + 8);                \
        __half2 h;                                                             \
        h = __floats2half2_rn(v0.x, v0.y); AH[rg][0] = *(u32*)&h;              \
        float2 r0 = __half22float2(h);                                         \
        h = __floats2half2_rn(v0.x - r0.x, v0.y - r0.y); AL[rg][0] = *(u32*)&h;\
        h = __floats2half2_rn(v1.x, v1.y); AH[rg][1] = *(u32*)&h;              \
        float2 r1 = __half22float2(h);                                         \
        h = __floats2half2_rn(v1.x - r1.x, v1.y - r1.y); AL[rg][1] = *(u32*)&h;\
        h = __floats2half2_rn(v2.x, v2.y); AH[rg][2] = *(u32*)&h;              \
        float2 r2 = __half22float2(h);                                         \
        h = __floats2half2_rn(v2.x - r2.x, v2.y - r2.y); AL[rg][2] = *(u32*)&h;\
        h = __floats2half2_rn(v3.x, v3.y); AH[rg][3] = *(u32*)&h;              \
        float2 r3 = __half22float2(h);                                         \
        h = __floats2half2_rn(v3.x - r3.x, v3.y - r3.y); AL[rg][3] = *(u32*)&h;\
    }

// ===========================================================================
// Fused f/g/h projection, N-SPLIT.  CTA = 64 rows x 160 cols, 160 threads,
// grid (256, 2).  v=0: h cols 0-127 + f;  v=1: h cols 128-255 + g.
// smem: A 2x10240 fp32 + W 160x36x2x2 = 43520  ->  3 CTAs/SM.
// ===========================================================================
#define FGH_NCOL 160
#define FGH_SMEM (20480 + 2 * (FGH_NCOL * SW_STRIDE * 2))   // 43520

__global__ __launch_bounds__(160) void k_fgh(
    const float* __restrict__ x,
    const float* __restrict__ Wh, const float* __restrict__ bh,
    const float* __restrict__ Wf, const float* __restrict__ bf,
    const float* __restrict__ Wg, const float* __restrict__ bg)
{
    extern __shared__ __align__(16) char sm[];
    float* sA[2] = { (float*)sm, (float*)(sm + 10240) };
    __half* sWhi = (__half*)(sm + 20480);
    __half* sWlo = (__half*)(sm + 20480 + FGH_NCOL * SW_STRIDE * 2);
    u32 sAu[2] = { smem_u32(sA[0]), smem_u32(sA[1]) };

    const int tid = threadIdx.x, w = tid >> 5, lane = tid & 31;
    const int qr = lane >> 2, kq2 = (lane & 3) << 1;
    const int v = blockIdx.y;
    const int row0 = blockIdx.x * 64;
    const char* xrow = (const char*)(x + (size_t)row0 * 256);

    float acc[4][4][4] = {};

    // preload A stage 0 (512 chunks, 160 threads)
#pragma unroll
    for (int i = 0; i < 4; i++) {
        int e = tid + 160 * i;
        if (e < 512) {
            int r = e >> 3, s = e & 7;
            cpa16(sAu[0] + r * 160 + s * 16, xrow + (size_t)r * 1024 + s * 16);
        }
    }
    CP_COMMIT();

    for (int s = 0; s < 8; s++) {
        const int k0 = s * 32;
        __syncthreads();
        if (s < 7) {
#pragma unroll
            for (int i = 0; i < 4; i++) {
                int e = tid + 160 * i;
                if (e < 512) {
                    int r = e >> 3, seg = e & 7;
                    cpa16(sAu[(s + 1) & 1] + r * 160 + seg * 16,
                          xrow + (size_t)r * 1024 + (k0 + 32) * 4 + seg * 16);
                }
            }
        }
        CP_COMMIT();
        // convert W chunk: thread tid owns W-smem col tid
        {
            const float* wp; int stride;
            if (tid < 128)      { wp = Wh + v * 128 + tid;               stride = 256; }
            else                { wp = (v ? Wg : Wf) + (tid - 128);      stride = 32; }
#pragma unroll
            for (int k = 0; k < 32; k++) {
                float vv = wp[(size_t)(k0 + k) * stride];
                __half hi = __float2half_rn(vv);
                sWhi[tid * SW_STRIDE + k] = hi;
                sWlo[tid * SW_STRIDE + k] = __float2half_rn(vv - __half2float(hi));
            }
        }
        if (s < 7) { CP_WAIT1(); } else { CP_WAIT0(); }
        __syncthreads();

        const float* sa = sA[s & 1];
#pragma unroll
        for (int kc = 0; kc < 2; kc++) {
            CVT_A_FRAGS4(sa)
#pragma unroll
            for (int nt = 0; nt < 4; nt++) {
                const __half* bp  = sWhi + (w * 32 + nt * 8 + qr) * SW_STRIDE + kc * 16 + kq2;
                const __half* bpl = sWlo + (w * 32 + nt * 8 + qr) * SW_STRIDE + kc * 16 + kq2;
                u32 bh0 = *(const u32*)bp,  bh1 = *(const u32*)(bp + 8);
                u32 bl0 = *(const u32*)bpl, bl1 = *(const u32*)(bpl + 8);
#pragma unroll
                for (int rg = 0; rg < 4; rg++) {
                    mma16816(acc[rg][nt], AH[rg], bh0, bh1);
                    mma16816(acc[rg][nt], AL[rg], bh0, bh1);
                    mma16816(acc[rg][nt], AH[rg], bl0, bl1);
                }
            }
        }
    }
    __syncthreads();   // reuse smem for output staging

    if (w < 4) {
        // --- h warps: global h col = v*128 + w*32 + cl ---
        __half* reg = (__half*)(sm + w * 4096);
        const int cglob0 = v * 128 + w * 32;
#pragma unroll
        for (int nt = 0; nt < 4; nt++) {
            int cl = nt * 8 + kq2;
            float b0 = bh[cglob0 + cl], b1 = bh[cglob0 + cl + 1];
#pragma unroll
            for (int rg = 0; rg < 4; rg++) {
                int r = rg * 16 + qr;
                __half2 p0 = __floats2half2_rn(acc[rg][nt][0] + b0, acc[rg][nt][1] + b1);
                __half2 p1 = __floats2half2_rn(acc[rg][nt][2] + b0, acc[rg][nt][3] + b1);
                reg[cl * 64 + r]           = __low2half(p0);
                reg[(cl + 1) * 64 + r]     = __high2half(p0);
                reg[cl * 64 + r + 8]       = __low2half(p1);
                reg[(cl + 1) * 64 + r + 8] = __high2half(p1);
            }
        }
        __syncwarp();
        const size_t b = (size_t)(row0 >> 12);
        const int nl = row0 & 4095;
        __half* dstb = d_h16T + b * (size_t)CC * NN;
#pragma unroll
        for (int i = 0; i < 8; i++) {
            int u = i * 32 + lane;
            int cl = u >> 3, seg = u & 7;
            *(uint4*)(dstb + (size_t)(cglob0 + cl) * NN + nl + seg * 8) =
                *(const uint4*)(reg + cl * 64 + seg * 8);
        }
    } else {
        // --- warp 4: f (v=0) or g (v=1), stage [64 n][32 hi | 32 lo] ---
        __half* reg = (__half*)(sm + 16384);
        const float* bias = v ? bg : bf;
#pragma unroll
        for (int nt = 0; nt < 4; nt++) {
            int cl = nt * 8 + kq2;
            float b0 = bias[cl], b1 = bias[cl + 1];
#pragma unroll
            for (int rg = 0; rg < 4; rg++) {
#pragma unroll
                for (int half = 0; half < 2; half++) {
                    int r = rg * 16 + qr + half * 8;
                    float v0 = acc[rg][nt][half * 2] + b0;
                    float v1 = acc[rg][nt][half * 2 + 1] + b1;
                    __half h0 = __float2half_rn(v0);
                    __half h1 = __float2half_rn(v1);
                    reg[r * 64 + cl] = h0;
                    reg[r * 64 + cl + 1] = h1;
                    reg[r * 64 + 32 + cl] = __float2half_rn(v0 - __half2float(h0));
                    reg[r * 64 + 32 + cl + 1] = __float2half_rn(v1 - __half2float(h1));
                }
            }
        }
        __syncwarp();
        __half* dst = (v ? d_g16 : d_f16p) + (size_t)row0 * 64;
#pragma unroll
        for (int i = 0; i < 16; i++) {
            int u = i * 32 + lane;
            int r = u >> 3, seg = u & 7;
            *(uint4*)(dst + (size_t)r * 64 + seg * 8) = *(const uint4*)(reg + r * 64 + seg * 8);
        }
    }
}

// ===========================================================================
// v projection + residual, N-SPLIT.  CTA = 64 rows x 128 cols, 128 threads,
// grid (256, 2).  smem: 20480 + 128x36x2x2 = 38912  ->  3 CTAs/SM.
// ===========================================================================
#define VP_SMEM (20480 + 2 * (128 * SW_STRIDE * 2))   // 38912

__global__ __launch_bounds__(128) void k_vproj(
    const float* __restrict__ Wv, const float* __restrict__ bv,
    const float* __restrict__ x, float* __restrict__ out)
{
    extern __shared__ __align__(16) char sm[];
    float* sA[2] = { (float*)sm, (float*)(sm + 10240) };
    __half* sWhi = (__half*)(sm + 20480);
    __half* sWlo = (__half*)(sm + 20480 + 128 * SW_STRIDE * 2);
    u32 sAu[2] = { smem_u32(sA[0]), smem_u32(sA[1]) };

    const int tid = threadIdx.x, w = tid >> 5, lane = tid & 31;
    const int qr = lane >> 2, kq2 = (lane & 3) << 1;
    const int v = blockIdx.y;
    const int row0 = blockIdx.x * 64;
    const char* arow = (const char*)(d_o + (size_t)row0 * 256);

    float acc[4][4][4] = {};

#pragma unroll
    for (int i = 0; i < 4; i++) {
        int e = tid + 128 * i; int r = e >> 3, s = e & 7;
        cpa16(sAu[0] + r * 160 + s * 16, arow + (size_t)r * 1024 + s * 16);
    }
    CP_COMMIT();

    for (int s = 0; s < 8; s++) {
        const int k0 = s * 32;
        __syncthreads();
        if (s < 7) {
#pragma unroll
            for (int i = 0; i < 4; i++) {
                int e = tid + 128 * i; int r = e >> 3, seg = e & 7;
                cpa16(sAu[(s + 1) & 1] + r * 160 + seg * 16,
                      arow + (size_t)r * 1024 + (k0 + 32) * 4 + seg * 16);
            }
        }
        CP_COMMIT();
        {
            const int col = v * 128 + tid;
#pragma unroll
            for (int k = 0; k < 32; k++) {
                float vv = Wv[(size_t)(k0 + k) * 256 + col];
                __half hi = __float2half_rn(vv);
                sWhi[tid * SW_STRIDE + k] = hi;
                sWlo[tid * SW_STRIDE + k] = __float2half_rn(vv - __half2float(hi));
            }
        }
        if (s < 7) { CP_WAIT1(); } else { CP_WAIT0(); }
        __syncthreads();

        const float* sa = sA[s & 1];
#pragma unroll
        for (int kc = 0; kc < 2; kc++) {
            CVT_A_FRAGS4(sa)
#pragma unroll
            for (int nt = 0; nt < 4; nt++) {
                const __half* bp  = sWhi + (w * 32 + nt * 8 + qr) * SW_STRIDE + kc * 16 + kq2;
                const __half* bpl = sWlo + (w * 32 + nt * 8 + qr) * SW_STRIDE + kc * 16 + kq2;
                u32 bh0 = *(const u32*)bp,  bh1 = *(const u32*)(bp + 8);
                u32 bl0 = *(const u32*)bpl, bl1 = *(const u32*)(bpl + 8);
#pragma unroll
                for (int rg = 0; rg < 4; rg++) {
                    mma16816(acc[rg][nt], AH[rg], bh0, bh1);
                    mma16816(acc[rg][nt], AL[rg], bh0, bh1);
                    mma16816(acc[rg][nt], AH[rg], bl0, bl1);
                }
            }
        }
    }

#pragma unroll
    for (int nt = 0; nt < 4; nt++) {
        int c = v * 128 + w * 32 + nt * 8 + kq2;
        float b0 = bv[c], b1 = bv[c + 1];
#pragma unroll
        for (int rg = 0; rg < 4; rg++) {
#pragma unroll
            for (int half = 0; half < 2; half++) {
                int r = row0 + rg * 16 + qr + half * 8;
                float2 xr = *(const float2*)&x[(size_t)r * 256 + c];
                float2 o;
                o.x = acc[rg][nt][half * 2] + b0 + xr.x;
                o.y = acc[rg][nt][half * 2 + 1] + b1 + xr.y;
                *(float2*)&out[(size_t)r * 256 + c] = o;
            }
        }
    }
}

// ===========================================================================
// HMMA flash attention — byte-identical to measured R13 (best: ~154 us).
// CTA = 64 q rows (4 warps, 128 thr), key-tile 64, grid (64, 4).
// ===========================================================================
#define SF_STRIDE 144
#define SH_STRIDE 144
#define SF_BYTES (64 * SF_STRIDE)
#define SH_BYTES (256 * SH_STRIDE)
#define ATTN_SMEM (2 * SF_BYTES + 2 * SH_BYTES)   // 92160
#define ONES_H2 0x3C003C00u

__global__ __launch_bounds__(128) void k_attn()
{
    extern __shared__ __align__(16) char dsm[];
    u32 sFu[2] = { smem_u32(dsm), smem_u32(dsm + SF_BYTES) };
    u32 sHu[2] = { smem_u32(dsm + 2 * SF_BYTES), smem_u32(dsm + 2 * SF_BYTES + SH_BYTES) };

    const int tid = threadIdx.x;
    const int w = tid >> 5, lane = tid & 31;
    const int qr = lane >> 2;
    const int kq = (lane & 3) << 1;
    const int b = blockIdx.y, q0 = blockIdx.x * 64;

    const int mat = lane >> 3, ln8 = lane & 7;
    const u32 fOffLane = (u32)((8 * (mat >> 1) + ln8) * SF_STRIDE + (mat & 1) * 16);
    const u32 hOffLane = (u32)((8 * (mat >> 1) + ln8) * SH_STRIDE + (mat & 1) * 16);
    const u32 pAOffLane = (u32)(ln8 * SF_STRIDE + mat * 16);

    const char* fglob = (const char*)(d_f16p + (size_t)b * NN * 64);
    const char* hglob = (const char*)(d_h16T + (size_t)b * CC * NN);

    u32 Ghi[2][4], Glo[2][4];
    {
        const char* g0 = (const char*)(d_g16 + (size_t)(b * NN + q0 + 16 * w) * 64);
#pragma unroll
        for (int c = 0; c < 2; ++c) {
            int kb = 16 * c + kq;
            Ghi[c][0] = *(const u32*)(g0 + (size_t)qr * 128 + kb * 2);
            Ghi[c][1] = *(const u32*)(g0 + (size_t)(qr + 8) * 128 + kb * 2);
            Ghi[c][2] = *(const u32*)(g0 + (size_t)qr * 128 + (kb + 8) * 2);
            Ghi[c][3] = *(const u32*)(g0 + (size_t)(qr + 8) * 128 + (kb + 8) * 2);
            Glo[c][0] = *(const u32*)(g0 + (size_t)qr * 128 + 64 + kb * 2);
            Glo[c][1] = *(const u32*)(g0 + (size_t)(qr + 8) * 128 + 64 + kb * 2);
            Glo[c][2] = *(const u32*)(g0 + (size_t)qr * 128 + 64 + (kb + 8) * 2);
            Glo[c][3] = *(const u32*)(g0 + (size_t)(qr + 8) * 128 + 64 + (kb + 8) * 2);
        }
    }

    // ================= Pass A: row max (hi-only S) =================
    float mrow0 = -1e30f, mrow1 = -1e30f;
    {
#pragma unroll
        for (int i = 0; i < 4; i++) {
            int e = tid + 128 * i; int row = e >> 3, q = e & 7;
            cpa16(sFu[0] + row * SF_STRIDE + q * 16, fglob + row * 128 + q * 16);
        }
        CP_COMMIT();
    }
#pragma unroll 1
    for (int kt = 0; kt < 64; ++kt) {
        if (kt < 63) {
            const char* gb = fglob + (size_t)(kt + 1) * 8192;
            u32 sb = sFu[(kt + 1) & 1];
#pragma unroll
            for (int i = 0; i < 4; i++) {
                int e = tid + 128 * i; int row = e >> 3, q = e & 7;
                cpa16(sb + row * SF_STRIDE + q * 16, gb + row * 128 + q * 16);
            }
            CP_COMMIT();
            CP_WAIT1();
        } else {
            CP_WAIT0();
        }
        __syncthreads();
        const u32 fbu = sFu[kt & 1];
#pragma unroll
        for (int j = 0; j < 8; ++j) {
            float c4[4] = {0.f, 0.f, 0.f, 0.f};
            u32 r0, r1, r2, r3;
            ldsm4(r0, r1, r2, r3, fbu + (u32)(8 * j * SF_STRIDE) + pAOffLane);
            mma16816(c4, Ghi[0], r0, r1);
            mma16816(c4, Ghi[1], r2, r3);
            mrow0 = fmaxf(mrow0, fmaxf(c4[0], c4[1]));
            mrow1 = fmaxf(mrow1, fmaxf(c4[2], c4[3]));
        }
        __syncthreads();
    }
    mrow0 = fmaxf(mrow0, __shfl_xor_sync(0xffffffffu, mrow0, 1));
    mrow0 = fmaxf(mrow0, __shfl_xor_sync(0xffffffffu, mrow0, 2));
    mrow1 = fmaxf(mrow1, __shfl_xor_sync(0xffffffffu, mrow1, 1));
    mrow1 = fmaxf(mrow1, __shfl_xor_sync(0xffffffffu, mrow1, 2));
    const float mL0 = mrow0 * L2E, mL1 = mrow1 * L2E;

    // ================= Pass B =================
    float oa[32][4];
#pragma unroll
    for (int j = 0; j < 32; ++j) { oa[j][0] = oa[j][1] = oa[j][2] = oa[j][3] = 0.f; }
    float lacc[4] = {0.f, 0.f, 0.f, 0.f};

    {
#pragma unroll
        for (int i = 0; i < 4; i++) {
            int e = tid + 128 * i; int row = e >> 3, q = e & 7;
            cpa16(sFu[0] + row * SF_STRIDE + q * 16, fglob + row * 128 + q * 16);
        }
#pragma unroll
        for (int i = 0; i < 16; i++) {
            int e = tid + 128 * i; int row = e >> 3, q = e & 7;
            cpa16(sHu[0] + row * SH_STRIDE + q * 16, hglob + (size_t)row * 8192 + q * 16);
        }
        CP_COMMIT();
    }

#pragma unroll 1
    for (int kt = 0; kt < 64; ++kt) {
        if (kt < 63) {
            u32 sfb = sFu[(kt + 1) & 1], shb = sHu[(kt + 1) & 1];
            const char* gf = fglob + (size_t)(kt + 1) * 8192;
            const char* gh = hglob + (size_t)(kt + 1) * 128;
#pragma unroll
            for (int i = 0; i < 4; i++) {
                int e = tid + 128 * i; int row = e >> 3, q = e & 7;
                cpa16(sfb + row * SF_STRIDE + q * 16, gf + row * 128 + q * 16);
            }
#pragma unroll
            for (int i = 0; i < 16; i++) {
                int e = tid + 128 * i; int row = e >> 3, q = e & 7;
                cpa16(shb + row * SH_STRIDE + q * 16, gh + (size_t)row * 8192 + q * 16);
            }
            CP_COMMIT();
            CP_WAIT1();
        } else {
            CP_WAIT0();
        }
        __syncthreads();

        const u32 fbu = sFu[kt & 1];
        const u32 hbu = sHu[kt & 1];

#pragma unroll
        for (int kk = 0; kk < 4; ++kk) {
            float cA[4] = {0.f, 0.f, 0.f, 0.f};
            float cB[4] = {0.f, 0.f, 0.f, 0.f};
            const u32 fRow = fbu + (u32)(16 * kk * SF_STRIDE) + fOffLane;
#pragma unroll
            for (int c = 0; c < 2; ++c) {
                u32 ah0, ah1, bh0, bh1, al0, al1, bl0, bl1;
                ldsm4(ah0, ah1, bh0, bh1, fRow + 32 * c);
                ldsm4(al0, al1, bl0, bl1, fRow + 32 * c + 64);
                mma16816(cA, Ghi[c], ah0, ah1);
                mma16816(cB, Ghi[c], bh0, bh1);
                mma16816(cA, Glo[c], ah0, ah1);
                mma16816(cB, Glo[c], bh0, bh1);
                mma16816(cA, Ghi[c], al0, al1);
                mma16816(cB, Ghi[c], bl0, bl1);
            }
            u32 P[4];
            P[0] = f2h2u(exp2f(fmaf(cA[0], L2E, -mL0)), exp2f(fmaf(cA[1], L2E, -mL0)));
            P[1] = f2h2u(exp2f(fmaf(cA[2], L2E, -mL1)), exp2f(fmaf(cA[3], L2E, -mL1)));
            P[2] = f2h2u(exp2f(fmaf(cB[0], L2E, -mL0)), exp2f(fmaf(cB[1], L2E, -mL0)));
            P[3] = f2h2u(exp2f(fmaf(cB[2], L2E, -mL1)), exp2f(fmaf(cB[3], L2E, -mL1)));

            mma16816(lacc, P, ONES_H2, ONES_H2);

            const u32 hRow = hbu + (u32)(32 * kk) + hOffLane;
#pragma unroll
            for (int pr = 0; pr < 16; ++pr) {
                u32 r0, r1, r2, r3;
                ldsm4(r0, r1, r2, r3, hRow + (u32)(16 * pr * SH_STRIDE));
                mma16816(oa[2 * pr], P, r0, r1);
                mma16816(oa[2 * pr + 1], P, r2, r3);
            }
        }
        __syncthreads();
    }

    // ---- epilogue: o = O / li ----
    {
        float inv0 = 1.0f / lacc[0];
        float inv1 = 1.0f / lacc[2];
        float* op = d_o + ((size_t)b * NN + q0 + 16 * w) * 256;
#pragma unroll
        for (int j2 = 0; j2 < 32; ++j2) {
            int cc = 8 * j2 + kq;
            *(float2*)(op + (size_t)qr * 256 + cc) =
                make_float2(oa[j2][0] * inv0, oa[j2][1] * inv0);
            *(float2*)(op + (size_t)(qr + 8) * 256 + cc) =
                make_float2(oa[j2][2] * inv1, oa[j2][3] * inv1);
        }
    }
}

// ---------------------------------------------------------------------------
extern "C" void kernel_launch(void* const* d_in, const int* in_sizes, int n_in,
                              void* d_out, int out_size)
{
    const float* x  = (const float*)d_in[0];
    const float* Wf = (const float*)d_in[1];
    const float* bf = (const float*)d_in[2];
    const float* Wg = (const float*)d_in[3];
    const float* bg = (const float*)d_in[4];
    const float* Wh = (const float*)d_in[5];
    const float* bh = (const float*)d_in[6];
    const float* Wv = (const float*)d_in[7];
    const float* bv = (const float*)d_in[8];
    float* out = (float*)d_out;

    cudaFuncSetAttribute(k_fgh,   cudaFuncAttributeMaxDynamicSharedMemorySize, FGH_SMEM);
    cudaFuncSetAttribute(k_vproj, cudaFuncAttributeMaxDynamicSharedMemorySize, VP_SMEM);
    cudaFuncSetAttribute(k_attn,  cudaFuncAttributeMaxDynamicSharedMemorySize, ATTN_SMEM);

    k_fgh<<<dim3(256, 2), 160, FGH_SMEM>>>(x, Wh, bh, Wf, bf, Wg, bg);
    k_attn<<<dim3(64, 4), 128, ATTN_SMEM>>>();
    k_vproj<<<dim3(256, 2), 128, VP_SMEM>>>(Wv, bv, x, out);
}